// round 9
// baseline (speedup 1.0000x reference)
#include <cuda_runtime.h>
#include <cuda_bf16.h>
#include <cstdint>

// Problem constants
#define B_SZ   2048
#define D_SZ   128
#define C_SZ   100000
#define KNN    10

// Fused kernel tiling
#define SPLITC 18
#define TILES  87
#define SLICE  (TILES * 64)        // 5568; 18*5568 = 100224 >= 100000
#define BM     128
#define BN     64
#define SSTRIDE 136                // bf16 elems per smem row (128 + 8 pad)
#define TILEBYTES (BN * SSTRIDE * 2)   // 17408

// Scratch (device globals; no allocation allowed)
__device__ __align__(16) float          g_enc_norm[B_SZ];
__device__ __align__(16) __nv_bfloat16  g_enc_bf16[B_SZ * D_SZ];
__device__ __align__(16) float          g_mem_norm[C_SZ];
__device__ __align__(16) __nv_bfloat16  g_mem_bf16[(size_t)C_SZ * D_SZ];
__device__ float g_partial[(size_t)B_SZ * SPLITC * 4 * KNN];  // 720 cand/row

// ---------------------------------------------------------------------------
// helpers
// ---------------------------------------------------------------------------
__device__ __forceinline__ uint32_t smem_u32(const void* p) {
    return (uint32_t)__cvta_generic_to_shared(p);
}

__device__ __forceinline__ void ldsm4(uint32_t& r0, uint32_t& r1, uint32_t& r2, uint32_t& r3,
                                      uint32_t addr) {
    asm volatile("ldmatrix.sync.aligned.m8n8.x4.shared.b16 {%0,%1,%2,%3}, [%4];\n"
                 : "=r"(r0), "=r"(r1), "=r"(r2), "=r"(r3) : "r"(addr));
}

__device__ __forceinline__ void mma16816(float* c, const uint32_t* a, const uint32_t* b) {
    asm volatile(
        "mma.sync.aligned.m16n8k16.row.col.f32.bf16.bf16.f32 "
        "{%0,%1,%2,%3},{%4,%5,%6,%7},{%8,%9},{%0,%1,%2,%3};\n"
        : "+f"(c[0]), "+f"(c[1]), "+f"(c[2]), "+f"(c[3])
        : "r"(a[0]), "r"(a[1]), "r"(a[2]), "r"(a[3]), "r"(b[0]), "r"(b[1]));
}

__device__ __forceinline__ void cp_async16(uint32_t saddr, const void* gptr, int srcbytes) {
    asm volatile("cp.async.cg.shared.global [%0], [%1], 16, %2;\n"
                 :: "r"(saddr), "l"(gptr), "r"(srcbytes));
}
__device__ __forceinline__ void cp_commit() { asm volatile("cp.async.commit_group;\n"); }
__device__ __forceinline__ void cp_wait0()  { asm volatile("cp.async.wait_group 0;\n"); }

__device__ __forceinline__ void topk_insert(float* best, float v) {
    if (v < best[KNN - 1]) {
        best[KNN - 1] = v;
        #pragma unroll
        for (int i = KNN - 1; i > 0; i--) {
            float lo = fminf(best[i - 1], best[i]);
            float hi = fmaxf(best[i - 1], best[i]);
            best[i - 1] = lo; best[i] = hi;
        }
    }
}

// ---------------------------------------------------------------------------
// Kernel A: encoder  enc = relu(state@W1+b1)@W2 + b2  (fp32), + bf16 copy + norms
// ---------------------------------------------------------------------------
__global__ void __launch_bounds__(128) enc_kernel(
    const float* __restrict__ state, const float* __restrict__ W1,
    const float* __restrict__ b1, const float* __restrict__ W2,
    const float* __restrict__ b2)
{
    __shared__ float s_buf[8][128];
    __shared__ float s_norm[8];
    const int t = threadIdx.x;
    const int row0 = blockIdx.x * 8;

    #pragma unroll
    for (int r = 0; r < 8; r++) s_buf[r][t] = state[(row0 + r) * D_SZ + t];
    if (t < 8) s_norm[t] = 0.f;
    __syncthreads();

    float acc[8];
    #pragma unroll
    for (int r = 0; r < 8; r++) acc[r] = 0.f;
    #pragma unroll 4
    for (int k = 0; k < D_SZ; k++) {
        float w = W1[k * D_SZ + t];
        #pragma unroll
        for (int r = 0; r < 8; r++) acc[r] = fmaf(s_buf[r][k], w, acc[r]);
    }
    __syncthreads();
    {
        float bb = b1[t];
        #pragma unroll
        for (int r = 0; r < 8; r++) s_buf[r][t] = fmaxf(acc[r] + bb, 0.f);
    }
    __syncthreads();

    float acc2[8];
    #pragma unroll
    for (int r = 0; r < 8; r++) acc2[r] = 0.f;
    #pragma unroll 4
    for (int k = 0; k < D_SZ; k++) {
        float w = W2[k * D_SZ + t];
        #pragma unroll
        for (int r = 0; r < 8; r++) acc2[r] = fmaf(s_buf[r][k], w, acc2[r]);
    }
    {
        float b2v = b2[t];
        #pragma unroll
        for (int r = 0; r < 8; r++) {
            float e = acc2[r] + b2v;
            g_enc_bf16[(row0 + r) * D_SZ + t] = __float2bfloat16(e);
            atomicAdd(&s_norm[r], e * e);
        }
    }
    __syncthreads();
    if (t < 8) g_enc_norm[row0 + t] = s_norm[t];
}

// ---------------------------------------------------------------------------
// Kernel B: memory -> bf16 + row norms (half range per launch)
// ---------------------------------------------------------------------------
__global__ void __launch_bounds__(128) prep_mem_kernel(const float* __restrict__ mem, int base)
{
    const int warp = threadIdx.x >> 5, lane = threadIdx.x & 31;
    const int row = base + blockIdx.x * 4 + warp;
    if (row >= C_SZ) return;
    const float4 v = ((const float4*)(mem + (size_t)row * D_SZ))[lane];
    float nrm = v.x * v.x + v.y * v.y + v.z * v.z + v.w * v.w;
    __nv_bfloat162 p0 = __floats2bfloat162_rn(v.x, v.y);
    __nv_bfloat162 p1 = __floats2bfloat162_rn(v.z, v.w);
    __nv_bfloat162* dst = (__nv_bfloat162*)(g_mem_bf16 + (size_t)row * D_SZ + lane * 4);
    dst[0] = p0; dst[1] = p1;
    #pragma unroll
    for (int o = 16; o; o >>= 1) nrm += __shfl_xor_sync(0xffffffffu, nrm, o);
    if (lane == 0) g_mem_norm[row] = nrm;
}

// ---------------------------------------------------------------------------
// Kernel C: fused bf16 GEMM + squared-distance screening + register top-10
// grid (SPLITC, 16) = 288 CTAs, block 256, __launch_bounds__(256,3):
// 3 CTAs/SM (24 warps) to cover LDSM/HMMA latency -- the profiled bottleneck.
// Warp tile 16x64, A reloaded per k-step (no hoist; register diet for occ=3).
// Double-buffered cp.async B tiles (smem 69.6KB/CTA so 3 CTAs fit in 228KB).
// ---------------------------------------------------------------------------
__global__ void __launch_bounds__(256, 3) knn_kernel()
{
    extern __shared__ char smem[];
    __nv_bfloat16* s_enc = (__nv_bfloat16*)smem;                   // 34816 B
    char*          s_mem = smem + BM * SSTRIDE * 2;                // 2 x 17408 B
    __shared__ float s_enorm[BM];
    __shared__ float s_mnorm[2][BN];

    const int tid  = threadIdx.x;
    const int bx   = blockIdx.x;          // C slice
    const int by   = blockIdx.y;          // batch tile
    const int row0 = by * BM;
    const int cbase = bx * SLICE;

    // ---- persistent enc tile + norms
    for (int idx = tid; idx < BM * 16; idx += 256) {
        int r = idx >> 4, c8 = idx & 15;
        ((uint4*)(s_enc + r * SSTRIDE))[c8] =
            ((const uint4*)(g_enc_bf16 + (size_t)(row0 + r) * D_SZ))[c8];
    }
    if (tid < BM) s_enorm[tid] = g_enc_norm[row0 + tid];

    const uint32_t encBase = smem_u32(s_enc);
    const uint32_t memBase = smem_u32(s_mem);

    // ---- preload tile 0
    {
        #pragma unroll
        for (int i = 0; i < 4; i++) {
            int idx = i * 256 + tid;
            int r = idx >> 4, c8 = idx & 15;
            int c = cbase + r;
            int cc = (c < C_SZ) ? c : 0;
            cp_async16(memBase + (r * SSTRIDE + c8 * 8) * 2,
                       g_mem_bf16 + (size_t)cc * D_SZ + c8 * 8,
                       (c < C_SZ) ? 16 : 0);
        }
        if (tid < BN) {
            int c = cbase + tid;
            s_mnorm[0][tid] = (c < C_SZ) ? g_mem_norm[c] : 3.0e37f;
        }
        cp_commit();
    }

    const int warp = tid >> 5, lane = tid & 31;
    const int lr = lane & 15, lc8 = lane >> 4;
    const int g  = lane >> 2, tq = lane & 3;

    float best0[KNN], best1[KNN];
    #pragma unroll
    for (int i = 0; i < KNN; i++) { best0[i] = 3.0e37f; best1[i] = 3.0e37f; }

    const uint32_t aRow = encBase + (warp * 16 + lr) * SSTRIDE * 2 + lc8 * 16;

    for (int t = 0; t < TILES; t++) {
        cp_wait0();
        __syncthreads();          // tile t data + mnorm visible; prev iter done
        const int cur = t & 1;

        // ---- issue tile t+1 copy (overlaps MMA below)
        if (t + 1 < TILES) {
            const int c0n = cbase + (t + 1) * BN;
            const uint32_t nbuf = memBase + (1 - cur) * TILEBYTES;
            #pragma unroll
            for (int i = 0; i < 4; i++) {
                int idx = i * 256 + tid;
                int r = idx >> 4, c8 = idx & 15;
                int c = c0n + r;
                int cc = (c < C_SZ) ? c : 0;
                cp_async16(nbuf + (r * SSTRIDE + c8 * 8) * 2,
                           g_mem_bf16 + (size_t)cc * D_SZ + c8 * 8,
                           (c < C_SZ) ? 16 : 0);
            }
            if (tid < BN) {
                int c = c0n + tid;
                s_mnorm[1 - cur][tid] = (c < C_SZ) ? g_mem_norm[c] : 3.0e37f;
            }
        }
        cp_commit();

        // ---- MMA: 16 rows x 64 cols per warp; A reloaded per k-step
        float acc[8][4];
        #pragma unroll
        for (int ni = 0; ni < 8; ni++)
            #pragma unroll
            for (int q = 0; q < 4; q++) acc[ni][q] = 0.f;

        const uint32_t curBase = memBase + cur * TILEBYTES;
        #pragma unroll
        for (int ks = 0; ks < 8; ks++) {
            uint32_t a0, a1, a2, a3;
            ldsm4(a0, a1, a2, a3, aRow + ks * 32);
            uint32_t af[4] = {a0, a1, a2, a3};
            #pragma unroll
            for (int nb = 0; nb < 4; nb++) {
                uint32_t q0, q1, q2, q3;
                ldsm4(q0, q1, q2, q3,
                      curBase + ((nb * 16 + lr) * SSTRIDE + ks * 16 + lc8 * 8) * 2);
                uint32_t be[2] = {q0, q2};
                uint32_t bo[2] = {q1, q3};
                mma16816(acc[nb * 2 + 0], af, be);
                mma16816(acc[nb * 2 + 1], af, bo);
            }
        }

        // ---- epilogue: grouped screening, s = ||m||^2 - 2*dot (no sqrt)
        const float2* mn2 = (const float2*)s_mnorm[cur];
        #pragma unroll
        for (int ni = 0; ni < 8; ni += 2) {
            const float2 mp0 = mn2[(ni * 8 + 2 * tq) >> 1];
            const float2 mp1 = mn2[((ni + 1) * 8 + 2 * tq) >> 1];
            {   // row g
                float s0 = fmaf(-2.f, acc[ni][0],     mp0.x);
                float s1 = fmaf(-2.f, acc[ni][1],     mp0.y);
                float s2 = fmaf(-2.f, acc[ni + 1][0], mp1.x);
                float s3 = fmaf(-2.f, acc[ni + 1][1], mp1.y);
                float mm = fminf(fminf(s0, s1), fminf(s2, s3));
                if (mm < best0[KNN - 1]) {
                    topk_insert(best0, s0); topk_insert(best0, s1);
                    topk_insert(best0, s2); topk_insert(best0, s3);
                }
            }
            {   // row g+8
                float u0 = fmaf(-2.f, acc[ni][2],     mp0.x);
                float u1 = fmaf(-2.f, acc[ni][3],     mp0.y);
                float u2 = fmaf(-2.f, acc[ni + 1][2], mp1.x);
                float u3 = fmaf(-2.f, acc[ni + 1][3], mp1.y);
                float um = fminf(fminf(u0, u1), fminf(u2, u3));
                if (um < best1[KNN - 1]) {
                    topk_insert(best1, u0); topk_insert(best1, u1);
                    topk_insert(best1, u2); topk_insert(best1, u3);
                }
            }
        }
    }

    // ---- write partial top-10 (squared dist = enorm + screened)
    const int r0 = warp * 16 + g;
    const float e0 = s_enorm[r0], e1 = s_enorm[r0 + 8];
    float* dst0 = g_partial + ((size_t)((row0 + r0) * SPLITC + bx) * 4 + tq) * KNN;
    float* dst1 = g_partial + ((size_t)((row0 + r0 + 8) * SPLITC + bx) * 4 + tq) * KNN;
    #pragma unroll
    for (int i = 0; i < KNN; i++) {
        dst0[i] = e0 + best0[i];
        dst1[i] = e1 + best1[i];
    }
}

// ---------------------------------------------------------------------------
// Kernel D: merge 720 squared-dist candidates/row -> mean of 10 smallest sqrt.
// Per-lane streaming top-10 then warp extract-min x10.  1 warp per row.
// ---------------------------------------------------------------------------
__global__ void __launch_bounds__(256) merge_kernel(float* __restrict__ out)
{
    const int warp = threadIdx.x >> 5, lane = threadIdx.x & 31;
    const int row = blockIdx.x * 8 + warp;
    const int NC = SPLITC * 4 * KNN;                  // 720
    const float* src = g_partial + (size_t)row * NC;

    float best[KNN];
    #pragma unroll
    for (int i = 0; i < KNN; i++) best[i] = 3.0e37f;
    for (int idx = lane; idx < NC; idx += 32)
        topk_insert(best, src[idx]);

    float sum = 0.f;
    for (int it = 0; it < KNN; it++) {
        float gm = best[0];
        #pragma unroll
        for (int o = 16; o; o >>= 1) gm = fminf(gm, __shfl_xor_sync(0xffffffffu, gm, o));
        sum += sqrtf(fmaxf(gm, 1e-12f));
        unsigned mask = __ballot_sync(0xffffffffu, best[0] == gm);
        int leader = __ffs(mask) - 1;
        if (lane == leader) {
            #pragma unroll
            for (int i = 0; i < KNN - 1; i++) best[i] = best[i + 1];
            best[KNN - 1] = 3.0e37f;
        }
    }
    if (lane == 0) out[row] = sum * (1.0f / KNN);
}

// ---------------------------------------------------------------------------
// launch: enc(0) prepA(1) prepB(2) knn(3) merge(4)  -- ncu window lands on knn
// ---------------------------------------------------------------------------
extern "C" void kernel_launch(void* const* d_in, const int* in_sizes, int n_in,
                              void* d_out, int out_size)
{
    (void)in_sizes; (void)n_in; (void)out_size;
    const float* state  = (const float*)d_in[0];
    const float* W1     = (const float*)d_in[1];
    const float* b1     = (const float*)d_in[2];
    const float* W2     = (const float*)d_in[3];
    const float* b2     = (const float*)d_in[4];
    const float* memory = (const float*)d_in[5];
    float* out = (float*)d_out;

    const int smemC = BM * SSTRIDE * 2 + 2 * TILEBYTES;   // 69632 bytes
    cudaFuncSetAttribute(knn_kernel, cudaFuncAttributeMaxDynamicSharedMemorySize, smemC);

    enc_kernel<<<B_SZ / 8, 128>>>(state, W1, b1, W2, b2);
    prep_mem_kernel<<<12500, 128>>>(memory, 0);
    prep_mem_kernel<<<12500, 128>>>(memory, 50000);
    knn_kernel<<<dim3(SPLITC, B_SZ / BM), 256, smemC>>>();
    merge_kernel<<<B_SZ / 8, 256>>>(out);
}

// round 10
// speedup vs baseline: 1.0207x; 1.0207x over previous
#include <cuda_runtime.h>
#include <cuda_bf16.h>
#include <cstdint>

// Problem constants
#define B_SZ   2048
#define D_SZ   128
#define C_SZ   100000
#define KNN    10

// Fused kernel tiling
#define SPLITC 27
#define TILES  58
#define SLICE  (TILES * 64)        // 3712; 27*3712 = 100224 >= 100000
#define BM     128
#define BN     64
#define SSTRIDE 136                // bf16 elems per smem row (128 + 8 pad)
#define TILEBYTES (BN * SSTRIDE * 2)   // 17408

// Scratch (device globals; no allocation allowed)
__device__ __align__(16) float          g_enc_norm[B_SZ];
__device__ __align__(16) __nv_bfloat16  g_enc_bf16[B_SZ * D_SZ];
__device__ __align__(16) float          g_mem_norm[C_SZ];
__device__ __align__(16) __nv_bfloat16  g_mem_bf16[(size_t)C_SZ * D_SZ];
__device__ float g_partial[(size_t)B_SZ * SPLITC * 4 * KNN];  // 1080 cand/row

// ---------------------------------------------------------------------------
// helpers
// ---------------------------------------------------------------------------
__device__ __forceinline__ uint32_t smem_u32(const void* p) {
    return (uint32_t)__cvta_generic_to_shared(p);
}

__device__ __forceinline__ void ldsm4(uint32_t& r0, uint32_t& r1, uint32_t& r2, uint32_t& r3,
                                      uint32_t addr) {
    asm volatile("ldmatrix.sync.aligned.m8n8.x4.shared.b16 {%0,%1,%2,%3}, [%4];\n"
                 : "=r"(r0), "=r"(r1), "=r"(r2), "=r"(r3) : "r"(addr));
}

__device__ __forceinline__ void mma16816(float* c, const uint32_t* a, const uint32_t* b) {
    asm volatile(
        "mma.sync.aligned.m16n8k16.row.col.f32.bf16.bf16.f32 "
        "{%0,%1,%2,%3},{%4,%5,%6,%7},{%8,%9},{%0,%1,%2,%3};\n"
        : "+f"(c[0]), "+f"(c[1]), "+f"(c[2]), "+f"(c[3])
        : "r"(a[0]), "r"(a[1]), "r"(a[2]), "r"(a[3]), "r"(b[0]), "r"(b[1]));
}

__device__ __forceinline__ void cp_async16(uint32_t saddr, const void* gptr, int srcbytes) {
    asm volatile("cp.async.cg.shared.global [%0], [%1], 16, %2;\n"
                 :: "r"(saddr), "l"(gptr), "r"(srcbytes));
}
__device__ __forceinline__ void cp_commit() { asm volatile("cp.async.commit_group;\n"); }
__device__ __forceinline__ void cp_wait0()  { asm volatile("cp.async.wait_group 0;\n"); }

__device__ __forceinline__ void topk_insert(float* best, float v) {
    if (v < best[KNN - 1]) {
        best[KNN - 1] = v;
        #pragma unroll
        for (int i = KNN - 1; i > 0; i--) {
            float lo = fminf(best[i - 1], best[i]);
            float hi = fmaxf(best[i - 1], best[i]);
            best[i - 1] = lo; best[i] = hi;
        }
    }
}

// ---------------------------------------------------------------------------
// Kernel A: encoder  enc = relu(state@W1+b1)@W2 + b2  (fp32), + bf16 copy + norms
// ---------------------------------------------------------------------------
__global__ void __launch_bounds__(128) enc_kernel(
    const float* __restrict__ state, const float* __restrict__ W1,
    const float* __restrict__ b1, const float* __restrict__ W2,
    const float* __restrict__ b2)
{
    __shared__ float s_buf[8][128];
    __shared__ float s_norm[8];
    const int t = threadIdx.x;
    const int row0 = blockIdx.x * 8;

    #pragma unroll
    for (int r = 0; r < 8; r++) s_buf[r][t] = state[(row0 + r) * D_SZ + t];
    if (t < 8) s_norm[t] = 0.f;
    __syncthreads();

    float acc[8];
    #pragma unroll
    for (int r = 0; r < 8; r++) acc[r] = 0.f;
    #pragma unroll 4
    for (int k = 0; k < D_SZ; k++) {
        float w = W1[k * D_SZ + t];
        #pragma unroll
        for (int r = 0; r < 8; r++) acc[r] = fmaf(s_buf[r][k], w, acc[r]);
    }
    __syncthreads();
    {
        float bb = b1[t];
        #pragma unroll
        for (int r = 0; r < 8; r++) s_buf[r][t] = fmaxf(acc[r] + bb, 0.f);
    }
    __syncthreads();

    float acc2[8];
    #pragma unroll
    for (int r = 0; r < 8; r++) acc2[r] = 0.f;
    #pragma unroll 4
    for (int k = 0; k < D_SZ; k++) {
        float w = W2[k * D_SZ + t];
        #pragma unroll
        for (int r = 0; r < 8; r++) acc2[r] = fmaf(s_buf[r][k], w, acc2[r]);
    }
    {
        float b2v = b2[t];
        #pragma unroll
        for (int r = 0; r < 8; r++) {
            float e = acc2[r] + b2v;
            g_enc_bf16[(row0 + r) * D_SZ + t] = __float2bfloat16(e);
            atomicAdd(&s_norm[r], e * e);
        }
    }
    __syncthreads();
    if (t < 8) g_enc_norm[row0 + t] = s_norm[t];
}

// ---------------------------------------------------------------------------
// Kernel B: memory -> bf16 + row norms (half range per launch)
// ---------------------------------------------------------------------------
__global__ void __launch_bounds__(128) prep_mem_kernel(const float* __restrict__ mem, int base)
{
    const int warp = threadIdx.x >> 5, lane = threadIdx.x & 31;
    const int row = base + blockIdx.x * 4 + warp;
    if (row >= C_SZ) return;
    const float4 v = ((const float4*)(mem + (size_t)row * D_SZ))[lane];
    float nrm = v.x * v.x + v.y * v.y + v.z * v.z + v.w * v.w;
    __nv_bfloat162 p0 = __floats2bfloat162_rn(v.x, v.y);
    __nv_bfloat162 p1 = __floats2bfloat162_rn(v.z, v.w);
    __nv_bfloat162* dst = (__nv_bfloat162*)(g_mem_bf16 + (size_t)row * D_SZ + lane * 4);
    dst[0] = p0; dst[1] = p1;
    #pragma unroll
    for (int o = 16; o; o >>= 1) nrm += __shfl_xor_sync(0xffffffffu, nrm, o);
    if (lane == 0) g_mem_norm[row] = nrm;
}

// ---------------------------------------------------------------------------
// Kernel C: fused bf16 GEMM + squared-distance screening + register top-10
// grid (SPLITC=27, 16) = 432 CTAs (~2.92/SM vs 3-CTA capacity -> single wave
// at 24 warps/SM), block 256, __launch_bounds__(256,3), regs <= 80.
// Warp tile 16x64, A reloaded per k-step.  Double-buffered cp.async B tiles.
// ---------------------------------------------------------------------------
__global__ void __launch_bounds__(256, 3) knn_kernel()
{
    extern __shared__ char smem[];
    __nv_bfloat16* s_enc = (__nv_bfloat16*)smem;                   // 34816 B
    char*          s_mem = smem + BM * SSTRIDE * 2;                // 2 x 17408 B
    __shared__ float s_enorm[BM];
    __shared__ float s_mnorm[2][BN];

    const int tid  = threadIdx.x;
    const int bx   = blockIdx.x;          // C slice
    const int by   = blockIdx.y;          // batch tile
    const int row0 = by * BM;
    const int cbase = bx * SLICE;

    // ---- persistent enc tile + norms
    for (int idx = tid; idx < BM * 16; idx += 256) {
        int r = idx >> 4, c8 = idx & 15;
        ((uint4*)(s_enc + r * SSTRIDE))[c8] =
            ((const uint4*)(g_enc_bf16 + (size_t)(row0 + r) * D_SZ))[c8];
    }
    if (tid < BM) s_enorm[tid] = g_enc_norm[row0 + tid];

    const uint32_t encBase = smem_u32(s_enc);
    const uint32_t memBase = smem_u32(s_mem);

    // ---- preload tile 0
    {
        #pragma unroll
        for (int i = 0; i < 4; i++) {
            int idx = i * 256 + tid;
            int r = idx >> 4, c8 = idx & 15;
            int c = cbase + r;
            int cc = (c < C_SZ) ? c : 0;
            cp_async16(memBase + (r * SSTRIDE + c8 * 8) * 2,
                       g_mem_bf16 + (size_t)cc * D_SZ + c8 * 8,
                       (c < C_SZ) ? 16 : 0);
        }
        if (tid < BN) {
            int c = cbase + tid;
            s_mnorm[0][tid] = (c < C_SZ) ? g_mem_norm[c] : 3.0e37f;
        }
        cp_commit();
    }

    const int warp = tid >> 5, lane = tid & 31;
    const int lr = lane & 15, lc8 = lane >> 4;
    const int g  = lane >> 2, tq = lane & 3;

    float best0[KNN], best1[KNN];
    #pragma unroll
    for (int i = 0; i < KNN; i++) { best0[i] = 3.0e37f; best1[i] = 3.0e37f; }

    const uint32_t aRow = encBase + (warp * 16 + lr) * SSTRIDE * 2 + lc8 * 16;

    for (int t = 0; t < TILES; t++) {
        cp_wait0();
        __syncthreads();          // tile t data + mnorm visible; prev iter done
        const int cur = t & 1;

        // ---- issue tile t+1 copy (overlaps MMA below)
        if (t + 1 < TILES) {
            const int c0n = cbase + (t + 1) * BN;
            const uint32_t nbuf = memBase + (1 - cur) * TILEBYTES;
            #pragma unroll
            for (int i = 0; i < 4; i++) {
                int idx = i * 256 + tid;
                int r = idx >> 4, c8 = idx & 15;
                int c = c0n + r;
                int cc = (c < C_SZ) ? c : 0;
                cp_async16(nbuf + (r * SSTRIDE + c8 * 8) * 2,
                           g_mem_bf16 + (size_t)cc * D_SZ + c8 * 8,
                           (c < C_SZ) ? 16 : 0);
            }
            if (tid < BN) {
                int c = c0n + tid;
                s_mnorm[1 - cur][tid] = (c < C_SZ) ? g_mem_norm[c] : 3.0e37f;
            }
        }
        cp_commit();

        // ---- MMA: 16 rows x 64 cols per warp; A reloaded per k-step
        float acc[8][4];
        #pragma unroll
        for (int ni = 0; ni < 8; ni++)
            #pragma unroll
            for (int q = 0; q < 4; q++) acc[ni][q] = 0.f;

        const uint32_t curBase = memBase + cur * TILEBYTES;
        #pragma unroll
        for (int ks = 0; ks < 8; ks++) {
            uint32_t a0, a1, a2, a3;
            ldsm4(a0, a1, a2, a3, aRow + ks * 32);
            uint32_t af[4] = {a0, a1, a2, a3};
            #pragma unroll
            for (int nb = 0; nb < 4; nb++) {
                uint32_t q0, q1, q2, q3;
                ldsm4(q0, q1, q2, q3,
                      curBase + ((nb * 16 + lr) * SSTRIDE + ks * 16 + lc8 * 8) * 2);
                uint32_t be[2] = {q0, q2};
                uint32_t bo[2] = {q1, q3};
                mma16816(acc[nb * 2 + 0], af, be);
                mma16816(acc[nb * 2 + 1], af, bo);
            }
        }

        // ---- epilogue: grouped screening, s = ||m||^2 - 2*dot (no sqrt)
        const float2* mn2 = (const float2*)s_mnorm[cur];
        #pragma unroll
        for (int ni = 0; ni < 8; ni += 2) {
            const float2 mp0 = mn2[(ni * 8 + 2 * tq) >> 1];
            const float2 mp1 = mn2[((ni + 1) * 8 + 2 * tq) >> 1];
            {   // row g
                float s0 = fmaf(-2.f, acc[ni][0],     mp0.x);
                float s1 = fmaf(-2.f, acc[ni][1],     mp0.y);
                float s2 = fmaf(-2.f, acc[ni + 1][0], mp1.x);
                float s3 = fmaf(-2.f, acc[ni + 1][1], mp1.y);
                float mm = fminf(fminf(s0, s1), fminf(s2, s3));
                if (mm < best0[KNN - 1]) {
                    topk_insert(best0, s0); topk_insert(best0, s1);
                    topk_insert(best0, s2); topk_insert(best0, s3);
                }
            }
            {   // row g+8
                float u0 = fmaf(-2.f, acc[ni][2],     mp0.x);
                float u1 = fmaf(-2.f, acc[ni][3],     mp0.y);
                float u2 = fmaf(-2.f, acc[ni + 1][2], mp1.x);
                float u3 = fmaf(-2.f, acc[ni + 1][3], mp1.y);
                float um = fminf(fminf(u0, u1), fminf(u2, u3));
                if (um < best1[KNN - 1]) {
                    topk_insert(best1, u0); topk_insert(best1, u1);
                    topk_insert(best1, u2); topk_insert(best1, u3);
                }
            }
        }
    }

    // ---- write partial top-10 (squared dist = enorm + screened)
    const int r0 = warp * 16 + g;
    const float e0 = s_enorm[r0], e1 = s_enorm[r0 + 8];
    float* dst0 = g_partial + ((size_t)((row0 + r0) * SPLITC + bx) * 4 + tq) * KNN;
    float* dst1 = g_partial + ((size_t)((row0 + r0 + 8) * SPLITC + bx) * 4 + tq) * KNN;
    #pragma unroll
    for (int i = 0; i < KNN; i++) {
        dst0[i] = e0 + best0[i];
        dst1[i] = e1 + best1[i];
    }
}

// ---------------------------------------------------------------------------
// Kernel D: merge 1080 squared-dist candidates/row -> mean of 10 smallest sqrt.
// Per-lane streaming top-10 then warp extract-min x10.  1 warp per row.
// ---------------------------------------------------------------------------
__global__ void __launch_bounds__(256) merge_kernel(float* __restrict__ out)
{
    const int warp = threadIdx.x >> 5, lane = threadIdx.x & 31;
    const int row = blockIdx.x * 8 + warp;
    const int NC = SPLITC * 4 * KNN;                  // 1080
    const float* src = g_partial + (size_t)row * NC;

    float best[KNN];
    #pragma unroll
    for (int i = 0; i < KNN; i++) best[i] = 3.0e37f;
    for (int idx = lane; idx < NC; idx += 32)
        topk_insert(best, src[idx]);

    float sum = 0.f;
    for (int it = 0; it < KNN; it++) {
        float gm = best[0];
        #pragma unroll
        for (int o = 16; o; o >>= 1) gm = fminf(gm, __shfl_xor_sync(0xffffffffu, gm, o));
        sum += sqrtf(fmaxf(gm, 1e-12f));
        unsigned mask = __ballot_sync(0xffffffffu, best[0] == gm);
        int leader = __ffs(mask) - 1;
        if (lane == leader) {
            #pragma unroll
            for (int i = 0; i < KNN - 1; i++) best[i] = best[i + 1];
            best[KNN - 1] = 3.0e37f;
        }
    }
    if (lane == 0) out[row] = sum * (1.0f / KNN);
}

// ---------------------------------------------------------------------------
// launch: enc(0) prepA(1) prepB(2) knn(3) merge(4)  -- ncu window lands on knn
// ---------------------------------------------------------------------------
extern "C" void kernel_launch(void* const* d_in, const int* in_sizes, int n_in,
                              void* d_out, int out_size)
{
    (void)in_sizes; (void)n_in; (void)out_size;
    const float* state  = (const float*)d_in[0];
    const float* W1     = (const float*)d_in[1];
    const float* b1     = (const float*)d_in[2];
    const float* W2     = (const float*)d_in[3];
    const float* b2     = (const float*)d_in[4];
    const float* memory = (const float*)d_in[5];
    float* out = (float*)d_out;

    const int smemC = BM * SSTRIDE * 2 + 2 * TILEBYTES;   // 69632 bytes
    cudaFuncSetAttribute(knn_kernel, cudaFuncAttributeMaxDynamicSharedMemorySize, smemC);

    enc_kernel<<<B_SZ / 8, 128>>>(state, W1, b1, W2, b2);
    prep_mem_kernel<<<12500, 128>>>(memory, 0);
    prep_mem_kernel<<<12500, 128>>>(memory, 50000);
    knn_kernel<<<dim3(SPLITC, B_SZ / BM), 256, smemC>>>();
    merge_kernel<<<B_SZ / 8, 256>>>(out);
}

// round 11
// speedup vs baseline: 1.0769x; 1.0550x over previous
#include <cuda_runtime.h>
#include <cuda_bf16.h>
#include <cstdint>

// Problem constants
#define B_SZ   2048
#define D_SZ   128
#define C_SZ   100000
#define KNN    10

// Fused kernel tiling
#define SPLITC 18
#define TILES  87
#define SLICE  (TILES * 64)        // 5568; 18*5568 = 100224 >= 100000
#define BM     128
#define BN     64
#define SSTRIDE 136                // bf16 elems per smem row (128 + 8 pad)
#define TILEBYTES (BN * SSTRIDE * 2)   // 17408

// Scratch (device globals; no allocation allowed)
__device__ __align__(16) float          g_enc_norm[B_SZ];
__device__ __align__(16) __nv_bfloat16  g_enc_bf16[B_SZ * D_SZ];
__device__ __align__(16) float          g_mem_norm[C_SZ];
__device__ __align__(16) __nv_bfloat16  g_mem_bf16[(size_t)C_SZ * D_SZ];
__device__ float g_partial[(size_t)B_SZ * SPLITC * 4 * KNN];  // 720 cand/row

// ---------------------------------------------------------------------------
// helpers
// ---------------------------------------------------------------------------
__device__ __forceinline__ uint32_t smem_u32(const void* p) {
    return (uint32_t)__cvta_generic_to_shared(p);
}

__device__ __forceinline__ void ldsm4(uint32_t& r0, uint32_t& r1, uint32_t& r2, uint32_t& r3,
                                      uint32_t addr) {
    asm volatile("ldmatrix.sync.aligned.m8n8.x4.shared.b16 {%0,%1,%2,%3}, [%4];\n"
                 : "=r"(r0), "=r"(r1), "=r"(r2), "=r"(r3) : "r"(addr));
}

__device__ __forceinline__ void mma16816(float* c, const uint32_t* a, const uint32_t* b) {
    asm volatile(
        "mma.sync.aligned.m16n8k16.row.col.f32.bf16.bf16.f32 "
        "{%0,%1,%2,%3},{%4,%5,%6,%7},{%8,%9},{%0,%1,%2,%3};\n"
        : "+f"(c[0]), "+f"(c[1]), "+f"(c[2]), "+f"(c[3])
        : "r"(a[0]), "r"(a[1]), "r"(a[2]), "r"(a[3]), "r"(b[0]), "r"(b[1]));
}

__device__ __forceinline__ void cp_async16(uint32_t saddr, const void* gptr, int srcbytes) {
    asm volatile("cp.async.cg.shared.global [%0], [%1], 16, %2;\n"
                 :: "r"(saddr), "l"(gptr), "r"(srcbytes));
}
__device__ __forceinline__ void cp_commit() { asm volatile("cp.async.commit_group;\n"); }
__device__ __forceinline__ void cp_wait1()  { asm volatile("cp.async.wait_group 1;\n"); }

__device__ __forceinline__ void topk_insert(float* best, float v) {
    if (v < best[KNN - 1]) {
        best[KNN - 1] = v;
        #pragma unroll
        for (int i = KNN - 1; i > 0; i--) {
            float lo = fminf(best[i - 1], best[i]);
            float hi = fmaxf(best[i - 1], best[i]);
            best[i - 1] = lo; best[i] = hi;
        }
    }
}

// ---------------------------------------------------------------------------
// Kernel A: encoder  enc = relu(state@W1+b1)@W2 + b2  (fp32), + bf16 copy + norms
// ---------------------------------------------------------------------------
__global__ void __launch_bounds__(128) enc_kernel(
    const float* __restrict__ state, const float* __restrict__ W1,
    const float* __restrict__ b1, const float* __restrict__ W2,
    const float* __restrict__ b2)
{
    __shared__ float s_buf[8][128];
    __shared__ float s_norm[8];
    const int t = threadIdx.x;
    const int row0 = blockIdx.x * 8;

    #pragma unroll
    for (int r = 0; r < 8; r++) s_buf[r][t] = state[(row0 + r) * D_SZ + t];
    if (t < 8) s_norm[t] = 0.f;
    __syncthreads();

    float acc[8];
    #pragma unroll
    for (int r = 0; r < 8; r++) acc[r] = 0.f;
    #pragma unroll 4
    for (int k = 0; k < D_SZ; k++) {
        float w = W1[k * D_SZ + t];
        #pragma unroll
        for (int r = 0; r < 8; r++) acc[r] = fmaf(s_buf[r][k], w, acc[r]);
    }
    __syncthreads();
    {
        float bb = b1[t];
        #pragma unroll
        for (int r = 0; r < 8; r++) s_buf[r][t] = fmaxf(acc[r] + bb, 0.f);
    }
    __syncthreads();

    float acc2[8];
    #pragma unroll
    for (int r = 0; r < 8; r++) acc2[r] = 0.f;
    #pragma unroll 4
    for (int k = 0; k < D_SZ; k++) {
        float w = W2[k * D_SZ + t];
        #pragma unroll
        for (int r = 0; r < 8; r++) acc2[r] = fmaf(s_buf[r][k], w, acc2[r]);
    }
    {
        float b2v = b2[t];
        #pragma unroll
        for (int r = 0; r < 8; r++) {
            float e = acc2[r] + b2v;
            g_enc_bf16[(row0 + r) * D_SZ + t] = __float2bfloat16(e);
            atomicAdd(&s_norm[r], e * e);
        }
    }
    __syncthreads();
    if (t < 8) g_enc_norm[row0 + t] = s_norm[t];
}

// ---------------------------------------------------------------------------
// Kernel B: memory -> bf16 + row norms (single full-range launch)
// ---------------------------------------------------------------------------
__global__ void __launch_bounds__(128) prep_mem_kernel(const float* __restrict__ mem)
{
    const int warp = threadIdx.x >> 5, lane = threadIdx.x & 31;
    const int row = blockIdx.x * 4 + warp;
    if (row >= C_SZ) return;
    const float4 v = ((const float4*)(mem + (size_t)row * D_SZ))[lane];
    float nrm = v.x * v.x + v.y * v.y + v.z * v.z + v.w * v.w;
    __nv_bfloat162 p0 = __floats2bfloat162_rn(v.x, v.y);
    __nv_bfloat162 p1 = __floats2bfloat162_rn(v.z, v.w);
    __nv_bfloat162* dst = (__nv_bfloat162*)(g_mem_bf16 + (size_t)row * D_SZ + lane * 4);
    dst[0] = p0; dst[1] = p1;
    #pragma unroll
    for (int o = 16; o; o >>= 1) nrm += __shfl_xor_sync(0xffffffffu, nrm, o);
    if (lane == 0) g_mem_norm[row] = nrm;
}

// ---------------------------------------------------------------------------
// Kernel C: fused bf16 GEMM + squared-distance screening + register top-10
// (best measured config: 264.5us) grid (SPLITC, 16) = 288 CTAs (2/SM),
// block 256, warp tile 16x64, full 8-kstep A-fragment hoist,
// triple-buffered cp.async B tiles with wait_group 1.
// ---------------------------------------------------------------------------
__global__ void __launch_bounds__(256, 2) knn_kernel()
{
    extern __shared__ char smem[];
    __nv_bfloat16* s_enc = (__nv_bfloat16*)smem;                   // 34816 B
    char*          s_mem = smem + BM * SSTRIDE * 2;                // 3 x 17408 B
    __shared__ float s_enorm[BM];
    __shared__ float s_mnorm[3][BN];

    const int tid  = threadIdx.x;
    const int bx   = blockIdx.x;          // C slice
    const int by   = blockIdx.y;          // batch tile
    const int row0 = by * BM;
    const int cbase = bx * SLICE;

    // ---- persistent enc tile + norms
    for (int idx = tid; idx < BM * 16; idx += 256) {
        int r = idx >> 4, c8 = idx & 15;
        ((uint4*)(s_enc + r * SSTRIDE))[c8] =
            ((const uint4*)(g_enc_bf16 + (size_t)(row0 + r) * D_SZ))[c8];
    }
    if (tid < BM) s_enorm[tid] = g_enc_norm[row0 + tid];

    const uint32_t encBase = smem_u32(s_enc);
    const uint32_t memBase = smem_u32(s_mem);

    // ---- preload tiles 0 and 1 (two cp.async groups)
    #pragma unroll
    for (int pt = 0; pt < 2; pt++) {
        const uint32_t buf = memBase + pt * TILEBYTES;
        #pragma unroll
        for (int i = 0; i < 4; i++) {
            int idx = i * 256 + tid;
            int r = idx >> 4, c8 = idx & 15;
            int c = cbase + pt * BN + r;
            int cc = (c < C_SZ) ? c : 0;
            cp_async16(buf + (r * SSTRIDE + c8 * 8) * 2,
                       g_mem_bf16 + (size_t)cc * D_SZ + c8 * 8,
                       (c < C_SZ) ? 16 : 0);
        }
        if (tid < BN) {
            int c = cbase + pt * BN + tid;
            s_mnorm[pt][tid] = (c < C_SZ) ? g_mem_norm[c] : 3.0e37f;
        }
        cp_commit();
    }
    __syncthreads();    // enc tile visible

    const int warp = tid >> 5, lane = tid & 31;
    const int lr = lane & 15, lc8 = lane >> 4;
    const int g  = lane >> 2, tq = lane & 3;

    // ---- hoist A fragments (tile-invariant): 8 k-steps x 4 regs
    uint32_t afrag[8][4];
    #pragma unroll
    for (int ks = 0; ks < 8; ks++) {
        uint32_t addr = encBase + ((warp * 16 + lr) * SSTRIDE + ks * 16 + lc8 * 8) * 2;
        ldsm4(afrag[ks][0], afrag[ks][1], afrag[ks][2], afrag[ks][3], addr);
    }

    float best0[KNN], best1[KNN];
    #pragma unroll
    for (int i = 0; i < KNN; i++) { best0[i] = 3.0e37f; best1[i] = 3.0e37f; }

    int cur = 0, nxt = 2;       // buffer indices mod 3
    for (int t = 0; t < TILES; t++) {
        cp_wait1();               // copy(t) complete (oldest of <=2 outstanding)
        __syncthreads();          // visible to all; prev iter's MMA on buf nxt done

        // ---- issue tile t+2 copy into buf nxt (2 tiles of flight time)
        if (t + 2 < TILES) {
            const int c0n = cbase + (t + 2) * BN;
            const uint32_t nbuf = memBase + nxt * TILEBYTES;
            #pragma unroll
            for (int i = 0; i < 4; i++) {
                int idx = i * 256 + tid;
                int r = idx >> 4, c8 = idx & 15;
                int c = c0n + r;
                int cc = (c < C_SZ) ? c : 0;
                cp_async16(nbuf + (r * SSTRIDE + c8 * 8) * 2,
                           g_mem_bf16 + (size_t)cc * D_SZ + c8 * 8,
                           (c < C_SZ) ? 16 : 0);
            }
            if (tid < BN) {
                int c = c0n + tid;
                s_mnorm[nxt][tid] = (c < C_SZ) ? g_mem_norm[c] : 3.0e37f;
            }
        }
        cp_commit();              // always commit (empty groups complete instantly)

        // ---- MMA: 16 rows x 64 cols per warp, from buf cur
        float acc[8][4];
        #pragma unroll
        for (int ni = 0; ni < 8; ni++)
            #pragma unroll
            for (int q = 0; q < 4; q++) acc[ni][q] = 0.f;

        const uint32_t curBase = memBase + cur * TILEBYTES;
        #pragma unroll
        for (int ks = 0; ks < 8; ks++) {
            #pragma unroll
            for (int nb = 0; nb < 4; nb++) {
                uint32_t q0, q1, q2, q3;
                ldsm4(q0, q1, q2, q3,
                      curBase + ((nb * 16 + lr) * SSTRIDE + ks * 16 + lc8 * 8) * 2);
                uint32_t be[2] = {q0, q2};
                uint32_t bo[2] = {q1, q3};
                mma16816(acc[nb * 2 + 0], afrag[ks], be);
                mma16816(acc[nb * 2 + 1], afrag[ks], bo);
            }
        }

        // ---- epilogue: grouped screening, s = ||m||^2 - 2*dot (no sqrt)
        const float2* mn2 = (const float2*)s_mnorm[cur];
        #pragma unroll
        for (int ni = 0; ni < 8; ni += 2) {
            const float2 mp0 = mn2[(ni * 8 + 2 * tq) >> 1];
            const float2 mp1 = mn2[((ni + 1) * 8 + 2 * tq) >> 1];
            {   // row g
                float s0 = fmaf(-2.f, acc[ni][0],     mp0.x);
                float s1 = fmaf(-2.f, acc[ni][1],     mp0.y);
                float s2 = fmaf(-2.f, acc[ni + 1][0], mp1.x);
                float s3 = fmaf(-2.f, acc[ni + 1][1], mp1.y);
                float mm = fminf(fminf(s0, s1), fminf(s2, s3));
                if (mm < best0[KNN - 1]) {
                    topk_insert(best0, s0); topk_insert(best0, s1);
                    topk_insert(best0, s2); topk_insert(best0, s3);
                }
            }
            {   // row g+8
                float u0 = fmaf(-2.f, acc[ni][2],     mp0.x);
                float u1 = fmaf(-2.f, acc[ni][3],     mp0.y);
                float u2 = fmaf(-2.f, acc[ni + 1][2], mp1.x);
                float u3 = fmaf(-2.f, acc[ni + 1][3], mp1.y);
                float um = fminf(fminf(u0, u1), fminf(u2, u3));
                if (um < best1[KNN - 1]) {
                    topk_insert(best1, u0); topk_insert(best1, u1);
                    topk_insert(best1, u2); topk_insert(best1, u3);
                }
            }
        }

        cur = (cur == 2) ? 0 : cur + 1;
        nxt = (nxt == 2) ? 0 : nxt + 1;
    }

    // ---- write partial top-10 (squared dist = enorm + screened)
    const int r0 = warp * 16 + g;
    const float e0 = s_enorm[r0], e1 = s_enorm[r0 + 8];
    float* dst0 = g_partial + ((size_t)((row0 + r0) * SPLITC + bx) * 4 + tq) * KNN;
    float* dst1 = g_partial + ((size_t)((row0 + r0 + 8) * SPLITC + bx) * 4 + tq) * KNN;
    #pragma unroll
    for (int i = 0; i < KNN; i++) {
        dst0[i] = e0 + best0[i];
        dst1[i] = e1 + best1[i];
    }
}

// ---------------------------------------------------------------------------
// Kernel D: merge 720 squared-dist candidates/row -> mean of 10 smallest sqrt.
// Per-lane streaming top-10 then warp extract-min x10.  1 warp per row.
// ---------------------------------------------------------------------------
__global__ void __launch_bounds__(256) merge_kernel(float* __restrict__ out)
{
    const int warp = threadIdx.x >> 5, lane = threadIdx.x & 31;
    const int row = blockIdx.x * 8 + warp;
    const int NC = SPLITC * 4 * KNN;                  // 720
    const float* src = g_partial + (size_t)row * NC;

    float best[KNN];
    #pragma unroll
    for (int i = 0; i < KNN; i++) best[i] = 3.0e37f;
    for (int idx = lane; idx < NC; idx += 32)
        topk_insert(best, src[idx]);

    float sum = 0.f;
    for (int it = 0; it < KNN; it++) {
        float gm = best[0];
        #pragma unroll
        for (int o = 16; o; o >>= 1) gm = fminf(gm, __shfl_xor_sync(0xffffffffu, gm, o));
        sum += sqrtf(fmaxf(gm, 1e-12f));
        unsigned mask = __ballot_sync(0xffffffffu, best[0] == gm);
        int leader = __ffs(mask) - 1;
        if (lane == leader) {
            #pragma unroll
            for (int i = 0; i < KNN - 1; i++) best[i] = best[i + 1];
            best[KNN - 1] = 3.0e37f;
        }
    }
    if (lane == 0) out[row] = sum * (1.0f / KNN);
}

// ---------------------------------------------------------------------------
// launch: 4-launch shell (R2 layout): enc(0) prep(1) knn(2) merge(3)
// ---------------------------------------------------------------------------
extern "C" void kernel_launch(void* const* d_in, const int* in_sizes, int n_in,
                              void* d_out, int out_size)
{
    (void)in_sizes; (void)n_in; (void)out_size;
    const float* state  = (const float*)d_in[0];
    const float* W1     = (const float*)d_in[1];
    const float* b1     = (const float*)d_in[2];
    const float* W2     = (const float*)d_in[3];
    const float* b2     = (const float*)d_in[4];
    const float* memory = (const float*)d_in[5];
    float* out = (float*)d_out;

    const int smemC = BM * SSTRIDE * 2 + 3 * TILEBYTES;   // 87040 bytes
    cudaFuncSetAttribute(knn_kernel, cudaFuncAttributeMaxDynamicSharedMemorySize, smemC);

    enc_kernel<<<B_SZ / 8, 128>>>(state, W1, b1, W2, b2);
    prep_mem_kernel<<<C_SZ / 4, 128>>>(memory);
    knn_kernel<<<dim3(SPLITC, B_SZ / BM), 256, smemC>>>();
    merge_kernel<<<B_SZ / 8, 256>>>(out);
}

// round 12
// speedup vs baseline: 1.1564x; 1.0739x over previous
#include <cuda_runtime.h>
#include <cuda_bf16.h>
#include <cstdint>

// Problem constants
#define B_SZ   2048
#define D_SZ   128
#define C_SZ   100000
#define KNN    10

// Fused kernel tiling
#define SPLITC 18
#define TILES  87
#define SLICE  (TILES * 64)       // 5568; 18*5568 = 100224 >= 100000
#define BM     128
#define BN     64
#define SSTRIDE 136               // bf16 elems per smem row (128 + 8 pad)
#define TILEBYTES (BN * SSTRIDE * 2)   // 17408

// Scratch (device globals; no allocation allowed)
__device__ __align__(16) float          g_enc_norm[B_SZ];
__device__ __align__(16) __nv_bfloat16  g_enc_bf16[B_SZ * D_SZ];
__device__ __align__(16) float          g_mem_norm[C_SZ];
__device__ __align__(16) __nv_bfloat16  g_mem_bf16[(size_t)C_SZ * D_SZ];
__device__ float g_partial[(size_t)B_SZ * SPLITC * 4 * KNN];  // 720 cand/row

// ---------------------------------------------------------------------------
// helpers
// ---------------------------------------------------------------------------
__device__ __forceinline__ uint32_t smem_u32(const void* p) {
    return (uint32_t)__cvta_generic_to_shared(p);
}

__device__ __forceinline__ void ldsm4(uint32_t& r0, uint32_t& r1, uint32_t& r2, uint32_t& r3,
                                      uint32_t addr) {
    asm volatile("ldmatrix.sync.aligned.m8n8.x4.shared.b16 {%0,%1,%2,%3}, [%4];\n"
                 : "=r"(r0), "=r"(r1), "=r"(r2), "=r"(r3) : "r"(addr));
}

__device__ __forceinline__ void mma16816(float* c, const uint32_t* a, const uint32_t* b) {
    asm volatile(
        "mma.sync.aligned.m16n8k16.row.col.f32.bf16.bf16.f32 "
        "{%0,%1,%2,%3},{%4,%5,%6,%7},{%8,%9},{%0,%1,%2,%3};\n"
        : "+f"(c[0]), "+f"(c[1]), "+f"(c[2]), "+f"(c[3])
        : "r"(a[0]), "r"(a[1]), "r"(a[2]), "r"(a[3]), "r"(b[0]), "r"(b[1]));
}

__device__ __forceinline__ void cp_async16(uint32_t saddr, const void* gptr, int srcbytes) {
    asm volatile("cp.async.cg.shared.global [%0], [%1], 16, %2;\n"
                 :: "r"(saddr), "l"(gptr), "r"(srcbytes));
}
__device__ __forceinline__ void cp_commit() { asm volatile("cp.async.commit_group;\n"); }
__device__ __forceinline__ void cp_wait0()  { asm volatile("cp.async.wait_group 0;\n"); }

__device__ __forceinline__ void topk_insert(float* best, float v) {
    if (v < best[KNN - 1]) {
        best[KNN - 1] = v;
        #pragma unroll
        for (int i = KNN - 1; i > 0; i--) {
            float lo = fminf(best[i - 1], best[i]);
            float hi = fmaxf(best[i - 1], best[i]);
            best[i - 1] = lo; best[i] = hi;
        }
    }
}

// ---------------------------------------------------------------------------
// Fused prep kernel: blocks [0,256) run the encoder (8 batch rows each);
// blocks [256, 256+25000) convert memory rows (4 rows each).
// The two halves are data-independent; fusing hides the encoder under the
// memory-bound prep phase and removes one launch boundary.
// ---------------------------------------------------------------------------
#define ENC_BLOCKS 256
#define PREP_BLOCKS 25000

__global__ void __launch_bounds__(128) fused_prep_kernel(
    const float* __restrict__ state, const float* __restrict__ W1,
    const float* __restrict__ b1, const float* __restrict__ W2,
    const float* __restrict__ b2, const float* __restrict__ mem)
{
    __shared__ float s_buf[8][128];
    __shared__ float s_norm[8];
    const int t = threadIdx.x;

    if (blockIdx.x >= ENC_BLOCKS) {
        // ---- memory prep: 4 rows per block
        const int warp = t >> 5, lane = t & 31;
        const int row = (blockIdx.x - ENC_BLOCKS) * 4 + warp;
        if (row >= C_SZ) return;
        const float4 v = ((const float4*)(mem + (size_t)row * D_SZ))[lane];
        float nrm = v.x * v.x + v.y * v.y + v.z * v.z + v.w * v.w;
        __nv_bfloat162 p0 = __floats2bfloat162_rn(v.x, v.y);
        __nv_bfloat162 p1 = __floats2bfloat162_rn(v.z, v.w);
        __nv_bfloat162* dst = (__nv_bfloat162*)(g_mem_bf16 + (size_t)row * D_SZ + lane * 4);
        dst[0] = p0; dst[1] = p1;
        #pragma unroll
        for (int o = 16; o; o >>= 1) nrm += __shfl_xor_sync(0xffffffffu, nrm, o);
        if (lane == 0) g_mem_norm[row] = nrm;
        return;
    }

    // ---- encoder: enc = relu(state@W1+b1)@W2 + b2, bf16 copy + norms
    const int row0 = blockIdx.x * 8;

    #pragma unroll
    for (int r = 0; r < 8; r++) s_buf[r][t] = state[(row0 + r) * D_SZ + t];
    if (t < 8) s_norm[t] = 0.f;
    __syncthreads();

    float acc[8];
    #pragma unroll
    for (int r = 0; r < 8; r++) acc[r] = 0.f;
    #pragma unroll 4
    for (int k = 0; k < D_SZ; k++) {
        float w = W1[k * D_SZ + t];
        #pragma unroll
        for (int r = 0; r < 8; r++) acc[r] = fmaf(s_buf[r][k], w, acc[r]);
    }
    __syncthreads();
    {
        float bb = b1[t];
        #pragma unroll
        for (int r = 0; r < 8; r++) s_buf[r][t] = fmaxf(acc[r] + bb, 0.f);
    }
    __syncthreads();

    float acc2[8];
    #pragma unroll
    for (int r = 0; r < 8; r++) acc2[r] = 0.f;
    #pragma unroll 4
    for (int k = 0; k < D_SZ; k++) {
        float w = W2[k * D_SZ + t];
        #pragma unroll
        for (int r = 0; r < 8; r++) acc2[r] = fmaf(s_buf[r][k], w, acc2[r]);
    }
    {
        float b2v = b2[t];
        #pragma unroll
        for (int r = 0; r < 8; r++) {
            float e = acc2[r] + b2v;
            g_enc_bf16[(row0 + r) * D_SZ + t] = __float2bfloat16(e);
            atomicAdd(&s_norm[r], e * e);
        }
    }
    __syncthreads();
    if (t < 8) g_enc_norm[row0 + t] = s_norm[t];
}

// ---------------------------------------------------------------------------
// Kernel C: fused bf16 GEMM + squared-distance screening + register top-10
// (measured-best wall-clock config = Round-2 kernel)
// grid (SPLITC, 16) = 288 CTAs (2/SM), block 256.  Warp tile = 16 x 64.
// Double-buffered cp.async mem tiles (wait0 at loop top), one barrier per
// tile, full 8-kstep A-fragment hoist, grouped float2 screening epilogue.
// ---------------------------------------------------------------------------
__global__ void __launch_bounds__(256, 2) knn_kernel()
{
    extern __shared__ char smem[];
    __nv_bfloat16* s_enc = (__nv_bfloat16*)smem;                   // 34816 B
    char*          s_mem = smem + BM * SSTRIDE * 2;                // 2 x 17408 B
    __shared__ float s_enorm[BM];
    __shared__ float s_mnorm[2][BN];

    const int tid  = threadIdx.x;
    const int bx   = blockIdx.x;          // C slice
    const int by   = blockIdx.y;          // batch tile
    const int row0 = by * BM;
    const int cbase = bx * SLICE;

    // ---- persistent enc tile + norms
    for (int idx = tid; idx < BM * 16; idx += 256) {
        int r = idx >> 4, c8 = idx & 15;
        ((uint4*)(s_enc + r * SSTRIDE))[c8] =
            ((const uint4*)(g_enc_bf16 + (size_t)(row0 + r) * D_SZ))[c8];
    }
    if (tid < BM) s_enorm[tid] = g_enc_norm[row0 + tid];

    const uint32_t encBase = smem_u32(s_enc);
    const uint32_t memBase = smem_u32(s_mem);

    // ---- preload tile 0
    {
        #pragma unroll
        for (int i = 0; i < 4; i++) {
            int idx = i * 256 + tid;
            int r = idx >> 4, c8 = idx & 15;
            int c = cbase + r;
            int cc = (c < C_SZ) ? c : 0;
            cp_async16(memBase + (r * SSTRIDE + c8 * 8) * 2,
                       g_mem_bf16 + (size_t)cc * D_SZ + c8 * 8,
                       (c < C_SZ) ? 16 : 0);
        }
        if (tid < BN) {
            int c = cbase + tid;
            s_mnorm[0][tid] = (c < C_SZ) ? g_mem_norm[c] : 3.0e37f;
        }
        cp_commit();
    }
    __syncthreads();    // enc tile visible

    const int warp = tid >> 5, lane = tid & 31;
    const int lr = lane & 15, lc8 = lane >> 4;
    const int g  = lane >> 2, tq = lane & 3;

    // ---- hoist A fragments (tile-invariant): 8 k-steps x 4 regs
    uint32_t afrag[8][4];
    #pragma unroll
    for (int ks = 0; ks < 8; ks++) {
        uint32_t addr = encBase + ((warp * 16 + lr) * SSTRIDE + ks * 16 + lc8 * 8) * 2;
        ldsm4(afrag[ks][0], afrag[ks][1], afrag[ks][2], afrag[ks][3], addr);
    }

    float best0[KNN], best1[KNN];
    #pragma unroll
    for (int i = 0; i < KNN; i++) { best0[i] = 3.0e37f; best1[i] = 3.0e37f; }

    for (int t = 0; t < TILES; t++) {
        cp_wait0();
        __syncthreads();          // tile t data + mnorm visible; prev iter done
        const int cur = t & 1;

        // ---- issue tile t+1 copy (overlaps MMA below)
        if (t + 1 < TILES) {
            const int c0n = cbase + (t + 1) * BN;
            const uint32_t nbuf = memBase + (1 - cur) * TILEBYTES;
            #pragma unroll
            for (int i = 0; i < 4; i++) {
                int idx = i * 256 + tid;
                int r = idx >> 4, c8 = idx & 15;
                int c = c0n + r;
                int cc = (c < C_SZ) ? c : 0;
                cp_async16(nbuf + (r * SSTRIDE + c8 * 8) * 2,
                           g_mem_bf16 + (size_t)cc * D_SZ + c8 * 8,
                           (c < C_SZ) ? 16 : 0);
            }
            if (tid < BN) {
                int c = c0n + tid;
                s_mnorm[1 - cur][tid] = (c < C_SZ) ? g_mem_norm[c] : 3.0e37f;
            }
        }
        cp_commit();

        // ---- MMA: 16 rows x 64 cols per warp
        float acc[8][4];
        #pragma unroll
        for (int ni = 0; ni < 8; ni++)
            #pragma unroll
            for (int q = 0; q < 4; q++) acc[ni][q] = 0.f;

        const uint32_t curBase = memBase + cur * TILEBYTES;
        #pragma unroll
        for (int ks = 0; ks < 8; ks++) {
            #pragma unroll
            for (int nb = 0; nb < 4; nb++) {
                uint32_t q0, q1, q2, q3;
                ldsm4(q0, q1, q2, q3,
                      curBase + ((nb * 16 + lr) * SSTRIDE + ks * 16 + lc8 * 8) * 2);
                uint32_t be[2] = {q0, q2};
                uint32_t bo[2] = {q1, q3};
                mma16816(acc[nb * 2 + 0], afrag[ks], be);
                mma16816(acc[nb * 2 + 1], afrag[ks], bo);
            }
        }

        // ---- epilogue: grouped screening, s = ||m||^2 - 2*dot (no sqrt)
        const float2* mn2 = (const float2*)s_mnorm[cur];
        #pragma unroll
        for (int ni = 0; ni < 8; ni += 2) {
            const float2 mp0 = mn2[(ni * 8 + 2 * tq) >> 1];
            const float2 mp1 = mn2[((ni + 1) * 8 + 2 * tq) >> 1];
            {   // row g
                float s0 = fmaf(-2.f, acc[ni][0],     mp0.x);
                float s1 = fmaf(-2.f, acc[ni][1],     mp0.y);
                float s2 = fmaf(-2.f, acc[ni + 1][0], mp1.x);
                float s3 = fmaf(-2.f, acc[ni + 1][1], mp1.y);
                float mm = fminf(fminf(s0, s1), fminf(s2, s3));
                if (mm < best0[KNN - 1]) {
                    topk_insert(best0, s0); topk_insert(best0, s1);
                    topk_insert(best0, s2); topk_insert(best0, s3);
                }
            }
            {   // row g+8
                float u0 = fmaf(-2.f, acc[ni][2],     mp0.x);
                float u1 = fmaf(-2.f, acc[ni][3],     mp0.y);
                float u2 = fmaf(-2.f, acc[ni + 1][2], mp1.x);
                float u3 = fmaf(-2.f, acc[ni + 1][3], mp1.y);
                float um = fminf(fminf(u0, u1), fminf(u2, u3));
                if (um < best1[KNN - 1]) {
                    topk_insert(best1, u0); topk_insert(best1, u1);
                    topk_insert(best1, u2); topk_insert(best1, u3);
                }
            }
        }
    }

    // ---- write partial top-10 (squared dist = enorm + screened)
    const int r0 = warp * 16 + g;
    const float e0 = s_enorm[r0], e1 = s_enorm[r0 + 8];
    float* dst0 = g_partial + ((size_t)((row0 + r0) * SPLITC + bx) * 4 + tq) * KNN;
    float* dst1 = g_partial + ((size_t)((row0 + r0 + 8) * SPLITC + bx) * 4 + tq) * KNN;
    #pragma unroll
    for (int i = 0; i < KNN; i++) {
        dst0[i] = e0 + best0[i];
        dst1[i] = e1 + best1[i];
    }
}

// ---------------------------------------------------------------------------
// Kernel D: merge 720 squared-dist candidates/row -> mean of 10 smallest sqrt.
// Per-lane streaming top-10 then warp extract-min x10.  1 warp per row.
// ---------------------------------------------------------------------------
__global__ void __launch_bounds__(256) merge_kernel(float* __restrict__ out)
{
    const int warp = threadIdx.x >> 5, lane = threadIdx.x & 31;
    const int row = blockIdx.x * 8 + warp;
    const int NC = SPLITC * 4 * KNN;                  // 720
    const float* src = g_partial + (size_t)row * NC;

    float best[KNN];
    #pragma unroll
    for (int i = 0; i < KNN; i++) best[i] = 3.0e37f;
    for (int idx = lane; idx < NC; idx += 32)
        topk_insert(best, src[idx]);

    float sum = 0.f;
    for (int it = 0; it < KNN; it++) {
        float gm = best[0];
        #pragma unroll
        for (int o = 16; o; o >>= 1) gm = fminf(gm, __shfl_xor_sync(0xffffffffu, gm, o));
        sum += sqrtf(fmaxf(gm, 1e-12f));
        unsigned mask = __ballot_sync(0xffffffffu, best[0] == gm);
        int leader = __ffs(mask) - 1;
        if (lane == leader) {
            #pragma unroll
            for (int i = 0; i < KNN - 1; i++) best[i] = best[i + 1];
            best[KNN - 1] = 3.0e37f;
        }
    }
    if (lane == 0) out[row] = sum * (1.0f / KNN);
}

// ---------------------------------------------------------------------------
// launch: 3-launch shell: fused_prep(0) knn(1) merge(2)
// ---------------------------------------------------------------------------
extern "C" void kernel_launch(void* const* d_in, const int* in_sizes, int n_in,
                              void* d_out, int out_size)
{
    (void)in_sizes; (void)n_in; (void)out_size;
    const float* state  = (const float*)d_in[0];
    const float* W1     = (const float*)d_in[1];
    const float* b1     = (const float*)d_in[2];
    const float* W2     = (const float*)d_in[3];
    const float* b2     = (const float*)d_in[4];
    const float* memory = (const float*)d_in[5];
    float* out = (float*)d_out;

    const int smemC = BM * SSTRIDE * 2 + 2 * TILEBYTES;   // 69632 bytes
    cudaFuncSetAttribute(knn_kernel, cudaFuncAttributeMaxDynamicSharedMemorySize, smemC);

    fused_prep_kernel<<<ENC_BLOCKS + PREP_BLOCKS, 128>>>(state, W1, b1, W2, b2, memory);
    knn_kernel<<<dim3(SPLITC, B_SZ / BM), 256, smemC>>>();
    merge_kernel<<<B_SZ / 8, 256>>>(out);
}

// round 13
// speedup vs baseline: 1.1594x; 1.0026x over previous
#include <cuda_runtime.h>
#include <cuda_bf16.h>
#include <cstdint>

// Problem constants
#define B_SZ   2048
#define D_SZ   128
#define C_SZ   100000
#define KNN    10

// Fused kernel tiling
#define SPLITC 18
#define TILES  87
#define SLICE  (TILES * 64)       // 5568; 18*5568 = 100224 >= 100000
#define BM     128
#define BN     64
#define SSTRIDE 136               // bf16 elems per smem row (128 + 8 pad)
#define TILEBYTES (BN * SSTRIDE * 2)   // 17408

// Scratch (device globals; no allocation allowed)
__device__ __align__(16) float          g_enc_norm[B_SZ];
__device__ __align__(16) __nv_bfloat16  g_enc_bf16[B_SZ * D_SZ];
__device__ __align__(16) float          g_mem_norm[C_SZ];
__device__ __align__(16) __nv_bfloat16  g_mem_bf16[(size_t)C_SZ * D_SZ];
__device__ float g_partial[(size_t)B_SZ * SPLITC * 4 * KNN];  // 720 cand/row

// ---------------------------------------------------------------------------
// helpers
// ---------------------------------------------------------------------------
__device__ __forceinline__ uint32_t smem_u32(const void* p) {
    return (uint32_t)__cvta_generic_to_shared(p);
}

__device__ __forceinline__ void ldsm4(uint32_t& r0, uint32_t& r1, uint32_t& r2, uint32_t& r3,
                                      uint32_t addr) {
    asm volatile("ldmatrix.sync.aligned.m8n8.x4.shared.b16 {%0,%1,%2,%3}, [%4];\n"
                 : "=r"(r0), "=r"(r1), "=r"(r2), "=r"(r3) : "r"(addr));
}

__device__ __forceinline__ void mma16816(float* c, const uint32_t* a, const uint32_t* b) {
    asm volatile(
        "mma.sync.aligned.m16n8k16.row.col.f32.bf16.bf16.f32 "
        "{%0,%1,%2,%3},{%4,%5,%6,%7},{%8,%9},{%0,%1,%2,%3};\n"
        : "+f"(c[0]), "+f"(c[1]), "+f"(c[2]), "+f"(c[3])
        : "r"(a[0]), "r"(a[1]), "r"(a[2]), "r"(a[3]), "r"(b[0]), "r"(b[1]));
}

__device__ __forceinline__ void cp_async16(uint32_t saddr, const void* gptr, int srcbytes) {
    asm volatile("cp.async.cg.shared.global [%0], [%1], 16, %2;\n"
                 :: "r"(saddr), "l"(gptr), "r"(srcbytes));
}
__device__ __forceinline__ void cp_commit() { asm volatile("cp.async.commit_group;\n"); }
__device__ __forceinline__ void cp_wait0()  { asm volatile("cp.async.wait_group 0;\n"); }

__device__ __forceinline__ void topk_insert(float* best, float v) {
    if (v < best[KNN - 1]) {
        best[KNN - 1] = v;
        #pragma unroll
        for (int i = KNN - 1; i > 0; i--) {
            float lo = fminf(best[i - 1], best[i]);
            float hi = fmaxf(best[i - 1], best[i]);
            best[i - 1] = lo; best[i] = hi;
        }
    }
}

// ---------------------------------------------------------------------------
// Fused prep kernel (256 threads/block):
//   blocks [0, ENC_BLOCKS): encoder, 16 batch rows per block (2 x 128-thread halves)
//   blocks [ENC_BLOCKS, ENC_BLOCKS+PREP_BLOCKS): memory->bf16+norm, 32 rows/block,
//     8 lanes per row, 4 independent float4 loads per thread (MLP=4, coalesced).
// ---------------------------------------------------------------------------
#define ENC_BLOCKS 128
#define PREP_BLOCKS 3125           // 3125 * 32 = 100000 rows exactly

__global__ void __launch_bounds__(256) fused_prep_kernel(
    const float* __restrict__ state, const float* __restrict__ W1,
    const float* __restrict__ b1, const float* __restrict__ W2,
    const float* __restrict__ b2, const float* __restrict__ mem)
{
    const int t = threadIdx.x;

    if (blockIdx.x >= ENC_BLOCKS) {
        // ---- memory prep: 32 rows per block, MLP=4 per thread
        const int b   = blockIdx.x - ENC_BLOCKS;
        const int sub = t >> 3;            // 0..31: row within block
        const int ln  = t & 7;             // 0..7: lane within row
        const int row = b * 32 + sub;
        const float4* src = (const float4*)(mem + (size_t)row * D_SZ);

        float4 v[4];
        #pragma unroll
        for (int i = 0; i < 4; i++) v[i] = src[i * 8 + ln];   // 4 independent 128B-apart loads

        float nrm = 0.f;
        #pragma unroll
        for (int i = 0; i < 4; i++)
            nrm += v[i].x * v[i].x + v[i].y * v[i].y + v[i].z * v[i].z + v[i].w * v[i].w;

        __nv_bfloat162* dst = (__nv_bfloat162*)(g_mem_bf16 + (size_t)row * D_SZ);
        #pragma unroll
        for (int i = 0; i < 4; i++) {
            __nv_bfloat162 p0 = __floats2bfloat162_rn(v[i].x, v[i].y);
            __nv_bfloat162 p1 = __floats2bfloat162_rn(v[i].z, v[i].w);
            dst[(i * 8 + ln) * 2 + 0] = p0;
            dst[(i * 8 + ln) * 2 + 1] = p1;
        }
        // reduce norm across the 8-lane subgroup (lanes share upper bits)
        #pragma unroll
        for (int o = 4; o; o >>= 1) nrm += __shfl_xor_sync(0xffffffffu, nrm, o);
        if (ln == 0) g_mem_norm[row] = nrm;
        return;
    }

    // ---- encoder: 16 rows per block; two 128-thread halves of 8 rows each
    __shared__ float s_buf[16][128];
    __shared__ float s_norm[16];
    const int half = t >> 7;               // 0 or 1
    const int tt   = t & 127;
    const int row0 = blockIdx.x * 16 + half * 8;
    float (*buf)[128] = &s_buf[half * 8];

    #pragma unroll
    for (int r = 0; r < 8; r++) buf[r][tt] = state[(row0 + r) * D_SZ + tt];
    if (tt < 8) s_norm[half * 8 + tt] = 0.f;
    __syncthreads();

    float acc[8];
    #pragma unroll
    for (int r = 0; r < 8; r++) acc[r] = 0.f;
    #pragma unroll 4
    for (int k = 0; k < D_SZ; k++) {
        float w = W1[k * D_SZ + tt];
        #pragma unroll
        for (int r = 0; r < 8; r++) acc[r] = fmaf(buf[r][k], w, acc[r]);
    }
    __syncthreads();
    {
        float bb = b1[tt];
        #pragma unroll
        for (int r = 0; r < 8; r++) buf[r][tt] = fmaxf(acc[r] + bb, 0.f);
    }
    __syncthreads();

    float acc2[8];
    #pragma unroll
    for (int r = 0; r < 8; r++) acc2[r] = 0.f;
    #pragma unroll 4
    for (int k = 0; k < D_SZ; k++) {
        float w = W2[k * D_SZ + tt];
        #pragma unroll
        for (int r = 0; r < 8; r++) acc2[r] = fmaf(buf[r][k], w, acc2[r]);
    }
    {
        float b2v = b2[tt];
        #pragma unroll
        for (int r = 0; r < 8; r++) {
            float e = acc2[r] + b2v;
            g_enc_bf16[(row0 + r) * D_SZ + tt] = __float2bfloat16(e);
            atomicAdd(&s_norm[half * 8 + r], e * e);
        }
    }
    __syncthreads();
    if (t < 16) g_enc_norm[blockIdx.x * 16 + t] = s_norm[t];
}

// ---------------------------------------------------------------------------
// Kernel C: fused bf16 GEMM + squared-distance screening + register top-10
// (measured-best wall-clock config = Round-2 kernel, UNCHANGED)
// grid (SPLITC, 16) = 288 CTAs (2/SM), block 256.  Warp tile = 16 x 64.
// Double-buffered cp.async mem tiles, one barrier per tile, A-frags hoisted.
// ---------------------------------------------------------------------------
__global__ void __launch_bounds__(256, 2) knn_kernel()
{
    extern __shared__ char smem[];
    __nv_bfloat16* s_enc = (__nv_bfloat16*)smem;                   // 34816 B
    char*          s_mem = smem + BM * SSTRIDE * 2;                // 2 x 17408 B
    __shared__ float s_enorm[BM];
    __shared__ float s_mnorm[2][BN];

    const int tid  = threadIdx.x;
    const int bx   = blockIdx.x;          // C slice
    const int by   = blockIdx.y;          // batch tile
    const int row0 = by * BM;
    const int cbase = bx * SLICE;

    // ---- persistent enc tile + norms
    for (int idx = tid; idx < BM * 16; idx += 256) {
        int r = idx >> 4, c8 = idx & 15;
        ((uint4*)(s_enc + r * SSTRIDE))[c8] =
            ((const uint4*)(g_enc_bf16 + (size_t)(row0 + r) * D_SZ))[c8];
    }
    if (tid < BM) s_enorm[tid] = g_enc_norm[row0 + tid];

    const uint32_t encBase = smem_u32(s_enc);
    const uint32_t memBase = smem_u32(s_mem);

    // ---- preload tile 0
    {
        #pragma unroll
        for (int i = 0; i < 4; i++) {
            int idx = i * 256 + tid;
            int r = idx >> 4, c8 = idx & 15;
            int c = cbase + r;
            int cc = (c < C_SZ) ? c : 0;
            cp_async16(memBase + (r * SSTRIDE + c8 * 8) * 2,
                       g_mem_bf16 + (size_t)cc * D_SZ + c8 * 8,
                       (c < C_SZ) ? 16 : 0);
        }
        if (tid < BN) {
            int c = cbase + tid;
            s_mnorm[0][tid] = (c < C_SZ) ? g_mem_norm[c] : 3.0e37f;
        }
        cp_commit();
    }
    __syncthreads();    // enc tile visible

    const int warp = tid >> 5, lane = tid & 31;
    const int lr = lane & 15, lc8 = lane >> 4;
    const int g  = lane >> 2, tq = lane & 3;

    // ---- hoist A fragments (tile-invariant): 8 k-steps x 4 regs
    uint32_t afrag[8][4];
    #pragma unroll
    for (int ks = 0; ks < 8; ks++) {
        uint32_t addr = encBase + ((warp * 16 + lr) * SSTRIDE + ks * 16 + lc8 * 8) * 2;
        ldsm4(afrag[ks][0], afrag[ks][1], afrag[ks][2], afrag[ks][3], addr);
    }

    float best0[KNN], best1[KNN];
    #pragma unroll
    for (int i = 0; i < KNN; i++) { best0[i] = 3.0e37f; best1[i] = 3.0e37f; }

    for (int t = 0; t < TILES; t++) {
        cp_wait0();
        __syncthreads();          // tile t data + mnorm visible; prev iter done
        const int cur = t & 1;

        // ---- issue tile t+1 copy (overlaps MMA below)
        if (t + 1 < TILES) {
            const int c0n = cbase + (t + 1) * BN;
            const uint32_t nbuf = memBase + (1 - cur) * TILEBYTES;
            #pragma unroll
            for (int i = 0; i < 4; i++) {
                int idx = i * 256 + tid;
                int r = idx >> 4, c8 = idx & 15;
                int c = c0n + r;
                int cc = (c < C_SZ) ? c : 0;
                cp_async16(nbuf + (r * SSTRIDE + c8 * 8) * 2,
                           g_mem_bf16 + (size_t)cc * D_SZ + c8 * 8,
                           (c < C_SZ) ? 16 : 0);
            }
            if (tid < BN) {
                int c = c0n + tid;
                s_mnorm[1 - cur][tid] = (c < C_SZ) ? g_mem_norm[c] : 3.0e37f;
            }
        }
        cp_commit();

        // ---- MMA: 16 rows x 64 cols per warp
        float acc[8][4];
        #pragma unroll
        for (int ni = 0; ni < 8; ni++)
            #pragma unroll
            for (int q = 0; q < 4; q++) acc[ni][q] = 0.f;

        const uint32_t curBase = memBase + cur * TILEBYTES;
        #pragma unroll
        for (int ks = 0; ks < 8; ks++) {
            #pragma unroll
            for (int nb = 0; nb < 4; nb++) {
                uint32_t q0, q1, q2, q3;
                ldsm4(q0, q1, q2, q3,
                      curBase + ((nb * 16 + lr) * SSTRIDE + ks * 16 + lc8 * 8) * 2);
                uint32_t be[2] = {q0, q2};
                uint32_t bo[2] = {q1, q3};
                mma16816(acc[nb * 2 + 0], afrag[ks], be);
                mma16816(acc[nb * 2 + 1], afrag[ks], bo);
            }
        }

        // ---- epilogue: grouped screening, s = ||m||^2 - 2*dot (no sqrt)
        const float2* mn2 = (const float2*)s_mnorm[cur];
        #pragma unroll
        for (int ni = 0; ni < 8; ni += 2) {
            const float2 mp0 = mn2[(ni * 8 + 2 * tq) >> 1];
            const float2 mp1 = mn2[((ni + 1) * 8 + 2 * tq) >> 1];
            {   // row g
                float s0 = fmaf(-2.f, acc[ni][0],     mp0.x);
                float s1 = fmaf(-2.f, acc[ni][1],     mp0.y);
                float s2 = fmaf(-2.f, acc[ni + 1][0], mp1.x);
                float s3 = fmaf(-2.f, acc[ni + 1][1], mp1.y);
                float mm = fminf(fminf(s0, s1), fminf(s2, s3));
                if (mm < best0[KNN - 1]) {
                    topk_insert(best0, s0); topk_insert(best0, s1);
                    topk_insert(best0, s2); topk_insert(best0, s3);
                }
            }
            {   // row g+8
                float u0 = fmaf(-2.f, acc[ni][2],     mp0.x);
                float u1 = fmaf(-2.f, acc[ni][3],     mp0.y);
                float u2 = fmaf(-2.f, acc[ni + 1][2], mp1.x);
                float u3 = fmaf(-2.f, acc[ni + 1][3], mp1.y);
                float um = fminf(fminf(u0, u1), fminf(u2, u3));
                if (um < best1[KNN - 1]) {
                    topk_insert(best1, u0); topk_insert(best1, u1);
                    topk_insert(best1, u2); topk_insert(best1, u3);
                }
            }
        }
    }

    // ---- write partial top-10 (squared dist = enorm + screened)
    const int r0 = warp * 16 + g;
    const float e0 = s_enorm[r0], e1 = s_enorm[r0 + 8];
    float* dst0 = g_partial + ((size_t)((row0 + r0) * SPLITC + bx) * 4 + tq) * KNN;
    float* dst1 = g_partial + ((size_t)((row0 + r0 + 8) * SPLITC + bx) * 4 + tq) * KNN;
    #pragma unroll
    for (int i = 0; i < KNN; i++) {
        dst0[i] = e0 + best0[i];
        dst1[i] = e1 + best1[i];
    }
}

// ---------------------------------------------------------------------------
// Kernel D: merge 720 squared-dist candidates/row -> mean of 10 smallest sqrt.
// Per-lane streaming top-10 then warp extract-min x10.  1 warp per row.
// ---------------------------------------------------------------------------
__global__ void __launch_bounds__(256) merge_kernel(float* __restrict__ out)
{
    const int warp = threadIdx.x >> 5, lane = threadIdx.x & 31;
    const int row = blockIdx.x * 8 + warp;
    const int NC = SPLITC * 4 * KNN;                  // 720
    const float* src = g_partial + (size_t)row * NC;

    float best[KNN];
    #pragma unroll
    for (int i = 0; i < KNN; i++) best[i] = 3.0e37f;
    for (int idx = lane; idx < NC; idx += 32)
        topk_insert(best, src[idx]);

    float sum = 0.f;
    for (int it = 0; it < KNN; it++) {
        float gm = best[0];
        #pragma unroll
        for (int o = 16; o; o >>= 1) gm = fminf(gm, __shfl_xor_sync(0xffffffffu, gm, o));
        sum += sqrtf(fmaxf(gm, 1e-12f));
        unsigned mask = __ballot_sync(0xffffffffu, best[0] == gm);
        int leader = __ffs(mask) - 1;
        if (lane == leader) {
            #pragma unroll
            for (int i = 0; i < KNN - 1; i++) best[i] = best[i + 1];
            best[KNN - 1] = 3.0e37f;
        }
    }
    if (lane == 0) out[row] = sum * (1.0f / KNN);
}

// ---------------------------------------------------------------------------
// launch: 3-launch shell: fused_prep(0) knn(1) merge(2)
// ---------------------------------------------------------------------------
extern "C" void kernel_launch(void* const* d_in, const int* in_sizes, int n_in,
                              void* d_out, int out_size)
{
    (void)in_sizes; (void)n_in; (void)out_size;
    const float* state  = (const float*)d_in[0];
    const float* W1     = (const float*)d_in[1];
    const float* b1     = (const float*)d_in[2];
    const float* W2     = (const float*)d_in[3];
    const float* b2     = (const float*)d_in[4];
    const float* memory = (const float*)d_in[5];
    float* out = (float*)d_out;

    const int smemC = BM * SSTRIDE * 2 + 2 * TILEBYTES;   // 69632 bytes
    cudaFuncSetAttribute(knn_kernel, cudaFuncAttributeMaxDynamicSharedMemorySize, smemC);

    fused_prep_kernel<<<ENC_BLOCKS + PREP_BLOCKS, 256>>>(state, W1, b1, W2, b2, memory);
    knn_kernel<<<dim3(SPLITC, B_SZ / BM), 256, smemC>>>();
    merge_kernel<<<B_SZ / 8, 256>>>(out);
}